// round 1
// baseline (speedup 1.0000x reference)
#include <cuda_runtime.h>
#include <math.h>

// out[i] = sum_{j<512} r[batch[i][j]] + log(n_pos / n_neg)
// batch: [16384, 512] int32, r: [50257] float32, n_pos/n_neg: scalar ints.
//
// One warp per row: each lane loads 4x int4 (16 tokens), gathers 16 floats
// from r (L1/L2-resident, 201KB), then a warp shuffle reduction.

#define ROWS   16384
#define LEN    512

__global__ __launch_bounds__(256) void nb_score_kernel(
    const int* __restrict__ batch,
    const float* __restrict__ r,
    const int* __restrict__ n_pos,
    const int* __restrict__ n_neg,
    float* __restrict__ out)
{
    const int warps_per_block = blockDim.x >> 5;
    const int row  = blockIdx.x * warps_per_block + (threadIdx.x >> 5);
    const int lane = threadIdx.x & 31;
    if (row >= ROWS) return;

    // Vectorized index load: 512 ints per row = 128 int4; 32 lanes x 4 iters.
    const int4* bp = reinterpret_cast<const int4*>(batch + (size_t)row * LEN);

    float s = 0.0f;
#pragma unroll
    for (int i = 0; i < 4; i++) {
        int4 v = bp[lane + 32 * i];
        s += __ldg(r + v.x);
        s += __ldg(r + v.y);
        s += __ldg(r + v.z);
        s += __ldg(r + v.w);
    }

    // Warp reduction
#pragma unroll
    for (int o = 16; o > 0; o >>= 1)
        s += __shfl_xor_sync(0xFFFFFFFFu, s, o);

    if (lane == 0) {
        // Reading the low 32 bits is correct for little-endian int32 or int64
        // storage of a positive scalar < 2^31.
        float lp = logf((float)__ldg(n_pos) / (float)__ldg(n_neg));
        out[row] = s + lp;
    }
}

extern "C" void kernel_launch(void* const* d_in, const int* in_sizes, int n_in,
                              void* d_out, int out_size)
{
    const int*   batch = (const int*)  d_in[0];
    const float* r     = (const float*)d_in[1];
    const int*   npos  = (const int*)  d_in[2];
    const int*   nneg  = (const int*)  d_in[3];
    float*       out   = (float*)      d_out;

    const int threads = 256;                 // 8 warps = 8 rows per block
    const int blocks  = ROWS / (threads / 32);  // 2048
    nb_score_kernel<<<blocks, threads>>>(batch, r, npos, nneg, out);
}

// round 2
// speedup vs baseline: 1.2123x; 1.2123x over previous
#include <cuda_runtime.h>
#include <math.h>

// out[i] = sum_{j<512} r[batch[i][j]] + log(n_pos / n_neg)
// batch: [16384, 512] int32 (33.6 MB, streamed once from HBM)
// r:     [50257] fp32 (201 KB) -> staged entirely in dynamic shared memory.
//
// 148 CTAs (one per SM), 1024 threads each. Each CTA stages r into SMEM once,
// then its 32 warps process rows grid-strided (warp per row): each lane loads
// 4x int4 indices and does 16 SMEM gathers, then a shuffle reduction.

#define ROWS   16384
#define LEN    512
#define VOCAB  50257
#define NBLK   148
#define NTHR   1024

__global__ __launch_bounds__(NTHR, 1) void nb_smem_kernel(
    const int* __restrict__ batch,
    const float* __restrict__ r,
    const int* __restrict__ n_pos,
    const int* __restrict__ n_neg,
    float* __restrict__ out)
{
    extern __shared__ float rs[];

    const int tid = threadIdx.x;

    // ---- Stage r into SMEM (vectorized float4) ----
    {
        const int n4 = VOCAB / 4;                       // 12564
        const float4* __restrict__ r4 = reinterpret_cast<const float4*>(r);
        float4* rs4 = reinterpret_cast<float4*>(rs);
        for (int i = tid; i < n4; i += NTHR)
            rs4[i] = r4[i];
        const int rem = VOCAB - n4 * 4;                 // 1
        if (tid < rem)
            rs[n4 * 4 + tid] = r[n4 * 4 + tid];
    }
    __syncthreads();

    const int warp = tid >> 5;
    const int lane = tid & 31;

    // log prior (tiny; read low 32 bits of the scalar — correct for LE int32/int64)
    const float lp = logf((float)__ldg(n_pos) / (float)__ldg(n_neg));

    // ---- Warp per row, grid-strided ----
    for (int row = blockIdx.x * 32 + warp; row < ROWS; row += NBLK * 32) {
        const int4* __restrict__ bp =
            reinterpret_cast<const int4*>(batch + (size_t)row * LEN);

        float s = 0.0f;
#pragma unroll
        for (int i = 0; i < 4; i++) {
            int4 v = bp[lane + 32 * i];
            s += rs[v.x];
            s += rs[v.y];
            s += rs[v.z];
            s += rs[v.w];
        }

#pragma unroll
        for (int o = 16; o > 0; o >>= 1)
            s += __shfl_xor_sync(0xFFFFFFFFu, s, o);

        if (lane == 0)
            out[row] = s + lp;
    }
}

extern "C" void kernel_launch(void* const* d_in, const int* in_sizes, int n_in,
                              void* d_out, int out_size)
{
    const int*   batch = (const int*)  d_in[0];
    const float* r     = (const float*)d_in[1];
    const int*   npos  = (const int*)  d_in[2];
    const int*   nneg  = (const int*)  d_in[3];
    float*       out   = (float*)      d_out;

    const int smem_bytes = ((VOCAB * 4 + 15) / 16) * 16;   // 201040 B

    static int configured = 0;
    if (!configured) {
        cudaFuncSetAttribute(nb_smem_kernel,
                             cudaFuncAttributeMaxDynamicSharedMemorySize,
                             smem_bytes);
        configured = 1;
    }

    nb_smem_kernel<<<NBLK, NTHR, smem_bytes>>>(batch, r, npos, nneg, out);
}

// round 3
// speedup vs baseline: 1.3995x; 1.1544x over previous
#include <cuda_runtime.h>
#include <math.h>

// out[i] = sum_{j<512} r[batch[i][j]] + log(n_pos / n_neg)
// r (201KB) staged in SMEM; indices streamed from HBM with a 2-row
// software pipeline (process pair N while pair N+1's loads are in flight).

#define ROWS   16384
#define LEN    512
#define VOCAB  50257
#define NBLK   148
#define NTHR   512
#define NWARP  (NTHR / 32)           // 16
#define GWARPS (NBLK * NWARP)        // 2368 warps, stride between pair rows

__device__ __forceinline__ void load_row(const int* __restrict__ batch,
                                         int row, int lane, int4* v)
{
    const int4* __restrict__ bp =
        reinterpret_cast<const int4*>(batch + (size_t)row * LEN);
#pragma unroll
    for (int i = 0; i < 4; i++)
        v[i] = bp[lane + 32 * i];
}

__global__ __launch_bounds__(NTHR, 1) void nb_pipe_kernel(
    const int* __restrict__ batch,
    const float* __restrict__ r,
    const int* __restrict__ n_pos,
    const int* __restrict__ n_neg,
    float* __restrict__ out)
{
    extern __shared__ float rs[];
    const int tid = threadIdx.x;

    // ---- Stage r into SMEM (float4) ----
    {
        const int n4 = VOCAB / 4;   // 12564
        const float4* __restrict__ r4 = reinterpret_cast<const float4*>(r);
        float4* rs4 = reinterpret_cast<float4*>(rs);
        for (int i = tid; i < n4; i += NTHR)
            rs4[i] = r4[i];
        if (tid == 0)
            rs[VOCAB - 1] = r[VOCAB - 1];
    }
    __syncthreads();

    const int warp = tid >> 5;
    const int lane = tid & 31;
    const int gw   = blockIdx.x * NWARP + warp;

    const float lp = logf((float)__ldg(n_pos) / (float)__ldg(n_neg));

    // ---- Pipelined pair loop ----
    int4 c0[4], c1[4];
    int  r0 = gw;
    bool v1 = false;

    if (r0 < ROWS) {
        load_row(batch, r0, lane, c0);
        if (r0 + GWARPS < ROWS) { load_row(batch, r0 + GWARPS, lane, c1); v1 = true; }
    }

    for (; r0 < ROWS; r0 += 2 * GWARPS) {
        // Prefetch next pair while we compute on the current one.
        int4 n0[4], n1[4];
        const int nr0 = r0 + 2 * GWARPS;
        bool nv1 = false;
        if (nr0 < ROWS) {
            load_row(batch, nr0, lane, n0);
            if (nr0 + GWARPS < ROWS) { load_row(batch, nr0 + GWARPS, lane, n1); nv1 = true; }
        }

        // Gather both rows, 2 accumulators each to break FADD chains.
        float a0 = 0.f, b0 = 0.f, a1 = 0.f, b1 = 0.f;
#pragma unroll
        for (int i = 0; i < 4; i++) {
            a0 += rs[c0[i].x];  b0 += rs[c0[i].y];
            a0 += rs[c0[i].z];  b0 += rs[c0[i].w];
        }
        if (v1) {
#pragma unroll
            for (int i = 0; i < 4; i++) {
                a1 += rs[c1[i].x];  b1 += rs[c1[i].y];
                a1 += rs[c1[i].z];  b1 += rs[c1[i].w];
            }
        }
        float s0 = a0 + b0;
        float s1 = a1 + b1;

        // Interleaved dual shuffle reductions (latencies overlap).
#pragma unroll
        for (int o = 16; o > 0; o >>= 1) {
            s0 += __shfl_xor_sync(0xFFFFFFFFu, s0, o);
            s1 += __shfl_xor_sync(0xFFFFFFFFu, s1, o);
        }

        if (lane == 0) {
            out[r0] = s0 + lp;
            if (v1) out[r0 + GWARPS] = s1 + lp;
        }

        // Rotate pipeline.
#pragma unroll
        for (int i = 0; i < 4; i++) { c0[i] = n0[i]; c1[i] = n1[i]; }
        v1 = nv1;
    }
}

extern "C" void kernel_launch(void* const* d_in, const int* in_sizes, int n_in,
                              void* d_out, int out_size)
{
    const int*   batch = (const int*)  d_in[0];
    const float* r     = (const float*)d_in[1];
    const int*   npos  = (const int*)  d_in[2];
    const int*   nneg  = (const int*)  d_in[3];
    float*       out   = (float*)      d_out;

    const int smem_bytes = ((VOCAB * 4 + 15) / 16) * 16;   // 201040 B

    static int configured = 0;
    if (!configured) {
        cudaFuncSetAttribute(nb_pipe_kernel,
                             cudaFuncAttributeMaxDynamicSharedMemorySize,
                             smem_bytes);
        configured = 1;
    }

    nb_pipe_kernel<<<NBLK, NTHR, smem_bytes>>>(batch, r, npos, nneg, out);
}